// round 1
// baseline (speedup 1.0000x reference)
#include <cuda_runtime.h>
#include <cstdint>

// LeakySNN fused kernel: x1 = x@W1^T + b1 (fp32 GEMM, FFMA2-packed),
// 25-step LIF recurrence in registers, spk_sum . W2 reduction -> atomicAdd.
//
// Shapes (fixed by problem): B=32768, NI=256, NH=1024, NO=1, NUM_STEPS=25.

#define TB      256
#define BM      128
#define BN      64
#define BK      16
#define NIc     256
#define NHc     1024
#define NSTEPS  25
#define AS_STRIDE (BM + 2)   // 130, even -> keeps 8B alignment for u64 smem loads
#define BS_STRIDE (BN + 4)   // 68

typedef unsigned long long u64;

__device__ __forceinline__ u64 pack2(float lo, float hi) {
    u64 r;
    asm("mov.b64 %0, {%1, %2};" : "=l"(r)
        : "r"(__float_as_uint(lo)), "r"(__float_as_uint(hi)));
    return r;
}

__device__ __forceinline__ void unpack2(u64 v, float& lo, float& hi) {
    unsigned a, b;
    asm("mov.b64 {%0, %1}, %2;" : "=r"(a), "=r"(b) : "l"(v));
    lo = __uint_as_float(a);
    hi = __uint_as_float(b);
}

// Packed dual-FMA: acc.{lo,hi} += a.{lo,hi} * b.{lo,hi}  (Blackwell f32x2 path)
__device__ __forceinline__ void fma2(u64& acc, u64 a, u64 b) {
    asm("fma.rn.f32x2 %0, %1, %2, %0;" : "+l"(acc) : "l"(a), "l"(b));
}

__global__ void init_out_kernel(float* __restrict__ out,
                                const float* __restrict__ b2, int n) {
    int i = blockIdx.x * blockDim.x + threadIdx.x;
    if (i < n) out[i] = b2[0];
}

__global__ void __launch_bounds__(TB)
snn_fused_kernel(const float* __restrict__ x,
                 const float* __restrict__ W1,
                 const float* __restrict__ b1,
                 const float* __restrict__ W2,
                 const float* __restrict__ beta_p,
                 const float* __restrict__ thr,
                 float* __restrict__ out) {
    __shared__ __align__(16) float As[BK * AS_STRIDE];  // x tile, k-major
    __shared__ __align__(16) float Bs[BK * BS_STRIDE];  // W1 tile, k-major

    const int tid = threadIdx.x;
    const int tx  = tid & 15;   // column group: cols tx*4 .. tx*4+3
    const int ty  = tid >> 4;   // row group:   rows ty*8 .. ty*8+7
    const int h0  = blockIdx.x * BN;
    const int b0  = blockIdx.y * BM;

    // Accumulators: 4 row-pairs x 4 cols, packed f32x2 along rows.
    u64 acc[4][4];
#pragma unroll
    for (int i = 0; i < 4; i++)
#pragma unroll
        for (int j = 0; j < 4; j++) acc[i][j] = 0ull;

    // ---- GEMM: x[b0:b0+128, :] @ W1[h0:h0+64, :]^T, K=256 in BK=16 stages ----
    const int lrow = tid >> 2;      // 0..63
    const int lkq  = tid & 3;       // 0..3 (which float4 along k within stage)
    const float* xg = x  + (size_t)b0 * NIc + (size_t)lrow * NIc + lkq * 4;
    const float* wg = W1 + (size_t)h0 * NIc + (size_t)lrow * NIc + lkq * 4;

    float4 xa, xb, wa;

    // prefetch stage 0
    xa = *(const float4*)(xg);
    xb = *(const float4*)(xg + 64 * NIc);
    wa = *(const float4*)(wg);

    auto store_stage = [&]() {
        const int kbase = lkq * 4;
#pragma unroll
        for (int c = 0; c < 4; c++) {
            float vx0 = (c == 0) ? xa.x : (c == 1) ? xa.y : (c == 2) ? xa.z : xa.w;
            float vx1 = (c == 0) ? xb.x : (c == 1) ? xb.y : (c == 2) ? xb.z : xb.w;
            float vw  = (c == 0) ? wa.x : (c == 1) ? wa.y : (c == 2) ? wa.z : wa.w;
            As[(kbase + c) * AS_STRIDE + lrow]      = vx0;
            As[(kbase + c) * AS_STRIDE + lrow + 64] = vx1;
            Bs[(kbase + c) * BS_STRIDE + lrow]      = vw;
        }
    };

    auto compute_stage = [&]() {
#pragma unroll
        for (int k = 0; k < BK; k++) {
            const float* arow = &As[k * AS_STRIDE + ty * 8];
            u64 a2[4];
            a2[0] = *(const u64*)(arow + 0);
            a2[1] = *(const u64*)(arow + 2);
            a2[2] = *(const u64*)(arow + 4);
            a2[3] = *(const u64*)(arow + 6);
            float4 bv = *(const float4*)&Bs[k * BS_STRIDE + tx * 4];
            u64 bb[4];
            bb[0] = pack2(bv.x, bv.x);
            bb[1] = pack2(bv.y, bv.y);
            bb[2] = pack2(bv.z, bv.z);
            bb[3] = pack2(bv.w, bv.w);
#pragma unroll
            for (int i = 0; i < 4; i++)
#pragma unroll
                for (int j = 0; j < 4; j++) fma2(acc[i][j], a2[i], bb[j]);
        }
    };

    store_stage();
    __syncthreads();

    const int NSTAGES = NIc / BK;  // 16
    for (int s = 1; s < NSTAGES; s++) {
        // prefetch next stage into registers (overlaps with compute below)
        xa = *(const float4*)(xg + s * BK);
        xb = *(const float4*)(xg + 64 * NIc + s * BK);
        wa = *(const float4*)(wg + s * BK);
        compute_stage();
        __syncthreads();
        store_stage();
        __syncthreads();
    }
    compute_stage();

    // ---- unpack x1, add b1 ----
    float x1v[8][4];
#pragma unroll
    for (int i = 0; i < 4; i++)
#pragma unroll
        for (int j = 0; j < 4; j++)
            unpack2(acc[i][j], x1v[2 * i][j], x1v[2 * i + 1][j]);

    float bb1[4], th[4], w2[4];
#pragma unroll
    for (int j = 0; j < 4; j++) {
        int h = h0 + tx * 4 + j;
        bb1[j] = b1[h];
        th[j]  = thr[h];
        w2[j]  = W2[h];
    }
#pragma unroll
    for (int r = 0; r < 8; r++)
#pragma unroll
        for (int j = 0; j < 4; j++) x1v[r][j] += bb1[j];

    const float beta = fminf(fmaxf(beta_p[0], 0.0f), 1.0f);

    // ---- 25-step LIF recurrence, fully in registers ----
    float mem[8][4], ssum[8][4];
#pragma unroll
    for (int r = 0; r < 8; r++)
#pragma unroll
        for (int j = 0; j < 4; j++) { mem[r][j] = 0.0f; ssum[r][j] = 0.0f; }

#pragma unroll 1
    for (int t = 0; t < NSTEPS; t++) {
#pragma unroll
        for (int r = 0; r < 8; r++) {
#pragma unroll
            for (int j = 0; j < 4; j++) {
                float m   = mem[r][j];
                float rst = (m > th[j]) ? th[j] : 0.0f;   // reset * thr
                m = fmaf(beta, m, x1v[r][j]) - rst;       // beta*mem + x1 - reset*thr
                mem[r][j] = m;
                ssum[r][j] += (m > th[j]) ? 1.0f : 0.0f;  // spike(mem_new - thr)
            }
        }
    }

    // ---- epilogue: out[b] += sum_h ssum * W2[h] (partial over this h-tile) ----
#pragma unroll
    for (int r = 0; r < 8; r++) {
        float p = ssum[r][0] * w2[0] + ssum[r][1] * w2[1] +
                  ssum[r][2] * w2[2] + ssum[r][3] * w2[3];
        // reduce across the 16 column-group lanes (width-16 segments of the warp)
#pragma unroll
        for (int off = 8; off > 0; off >>= 1)
            p += __shfl_down_sync(0xffffffffu, p, off, 16);
        if (tx == 0) atomicAdd(&out[b0 + ty * 8 + r], p);
    }
}

extern "C" void kernel_launch(void* const* d_in, const int* in_sizes, int n_in,
                              void* d_out, int out_size) {
    const float* x    = (const float*)d_in[0];
    const float* W1   = (const float*)d_in[1];
    const float* b1   = (const float*)d_in[2];
    const float* W2   = (const float*)d_in[3];
    const float* b2   = (const float*)d_in[4];
    const float* beta = (const float*)d_in[5];
    const float* thr  = (const float*)d_in[6];
    float* out = (float*)d_out;

    const int B = in_sizes[0] / NIc;  // 32768

    init_out_kernel<<<(B + 255) / 256, 256>>>(out, b2, B);

    dim3 grid(NHc / BN, B / BM);  // (16, 256): h fastest -> same x tile co-resident in L2
    snn_fused_kernel<<<grid, TB>>>(x, W1, b1, W2, beta, thr, out);
}

// round 3
// speedup vs baseline: 1.1195x; 1.1195x over previous
#include <cuda_runtime.h>
#include <cuda_fp16.h>
#include <cstdint>

// LeakySNN: x1 = x@W1^T + b1 via fp16 2-term-split mma.sync (3 products, f32 accum),
// 25-step LIF recurrence in registers (4 ops/elem-step), spk_sum.W2 -> atomicAdd.
// Shapes fixed: B=32768, NI=256, NH=1024, NO=1, NUM_STEPS=25.

#define NIc     256
#define NHc     1024
#define BTOT    32768
#define NSTEPS  25
#define BM      128
#define BN      64
#define BK      32
#define NSTAGE  (NIc / BK)   // 8

// smem stage layout in halves; row stride 40 halves (80B) -> conflict-free frags
#define A_HI   0
#define A_LO   5120
#define B_HI   10240
#define B_LO   12800
#define STG    15360          // halves per stage
#define SMEM_CONST 1024       // bytes reserved for b1/thr/w2 at front
#define SMEM_TOTAL (SMEM_CONST + 2 * STG * 2)   // 62464 bytes

// -------- scratch: pre-converted fp16 hi/lo copies of x and W1 --------
__device__ __half g_xhi[(size_t)BTOT * NIc];
__device__ __half g_xlo[(size_t)BTOT * NIc];
__device__ __half g_whi[(size_t)NHc * NIc];
__device__ __half g_wlo[(size_t)NHc * NIc];

__global__ void cvt_kernel(const float* __restrict__ src,
                           __half* __restrict__ hi, __half* __restrict__ lo,
                           int n4) {
    int i = blockIdx.x * blockDim.x + threadIdx.x;
    if (i >= n4) return;
    float4 v = *((const float4*)src + i);
    __half h0 = __float2half_rn(v.x), h1 = __float2half_rn(v.y);
    __half h2 = __float2half_rn(v.z), h3 = __float2half_rn(v.w);
    __half l0 = __float2half_rn(v.x - __half2float(h0));
    __half l1 = __float2half_rn(v.y - __half2float(h1));
    __half l2 = __float2half_rn(v.z - __half2float(h2));
    __half l3 = __float2half_rn(v.w - __half2float(h3));
    __half2* ph = (__half2*)(hi + (size_t)i * 4);
    __half2* pl = (__half2*)(lo + (size_t)i * 4);
    ph[0] = __halves2half2(h0, h1); ph[1] = __halves2half2(h2, h3);
    pl[0] = __halves2half2(l0, l1); pl[1] = __halves2half2(l2, l3);
}

__global__ void init_out_kernel(float* __restrict__ out,
                                const float* __restrict__ b2, int n) {
    int i = blockIdx.x * blockDim.x + threadIdx.x;
    if (i < n) out[i] = b2[0];
}

#define MMA16816(C, A, B) \
    asm volatile("mma.sync.aligned.m16n8k16.row.col.f32.f16.f16.f32 " \
        "{%0,%1,%2,%3}, {%4,%5,%6,%7}, {%8,%9}, {%0,%1,%2,%3};" \
        : "+f"((C)[0]), "+f"((C)[1]), "+f"((C)[2]), "+f"((C)[3]) \
        : "r"((A)[0]), "r"((A)[1]), "r"((A)[2]), "r"((A)[3]), \
          "r"((B)[0]), "r"((B)[1]))

__global__ void __launch_bounds__(256, 2)
snn_mma_kernel(const float* __restrict__ b1,
               const float* __restrict__ W2,
               const float* __restrict__ beta_p,
               const float* __restrict__ thr,
               float* __restrict__ out) {
    extern __shared__ __align__(16) char smem[];
    float* sB1 = (float*)smem;
    float* sTH = sB1 + 64;
    float* sW2 = sTH + 64;
    __half* stg = (__half*)(smem + SMEM_CONST);

    const int tid = threadIdx.x;
    const int l   = tid & 31;
    const int wid = tid >> 5;
    const int wm  = wid & 3;        // 4 warps along M (32 rows each)
    const int wn  = wid >> 2;       // 2 warps along N (32 cols each)
    const int h0  = blockIdx.x * BN;
    const int b0  = blockIdx.y * BM;

    if (tid < 64) {
        sB1[tid] = b1[h0 + tid];
        sTH[tid] = thr[h0 + tid];
        sW2[tid] = W2[h0 + tid];
    }

    // ---- gmem->smem staging indices ----
    const int rowA = tid >> 1, caOff = (tid & 1) * 16;
    const int rowB = tid >> 2, cbOff = (tid & 3) * 8;
    const __half* pxh = g_xhi + (size_t)(b0 + rowA) * NIc + caOff;
    const __half* pxl = g_xlo + (size_t)(b0 + rowA) * NIc + caOff;
    const __half* pwh = g_whi + (size_t)(h0 + rowB) * NIc + cbOff;
    const __half* pwl = g_wlo + (size_t)(h0 + rowB) * NIc + cbOff;
    const int smA = rowA * 40 + caOff;
    const int smB = rowB * 40 + cbOff;

    uint4 rah0, rah1, ral0, ral1, rbh, rbl;

    auto prefetch = [&](int s) {
        rah0 = *(const uint4*)(pxh + s * BK);
        rah1 = *(const uint4*)(pxh + s * BK + 8);
        ral0 = *(const uint4*)(pxl + s * BK);
        ral1 = *(const uint4*)(pxl + s * BK + 8);
        rbh  = *(const uint4*)(pwh + s * BK);
        rbl  = *(const uint4*)(pwl + s * BK);
    };
    auto store_stage = [&](int buf) {
        __half* t = stg + buf * STG;
        *(uint4*)(t + A_HI + smA)     = rah0;
        *(uint4*)(t + A_HI + smA + 8) = rah1;
        *(uint4*)(t + A_LO + smA)     = ral0;
        *(uint4*)(t + A_LO + smA + 8) = ral1;
        *(uint4*)(t + B_HI + smB)     = rbh;
        *(uint4*)(t + B_LO + smB)     = rbl;
    };

    float c[2][4][4];
#pragma unroll
    for (int mt = 0; mt < 2; mt++)
#pragma unroll
        for (int nt = 0; nt < 4; nt++)
#pragma unroll
            for (int r = 0; r < 4; r++) c[mt][nt][r] = 0.0f;

    const int lr = l >> 2;          // 0..7
    const int lq = (l & 3) * 2;     // 0,2,4,6

    auto compute_stage = [&](int buf) {
        const __half* sah = stg + buf * STG + A_HI;
        const __half* sal = stg + buf * STG + A_LO;
        const __half* sbh = stg + buf * STG + B_HI;
        const __half* sbl = stg + buf * STG + B_LO;
#pragma unroll
        for (int ks = 0; ks < 2; ks++) {
            const int kk = ks * 16;
            uint32_t ah[2][4], al[2][4], bh[4][2], bl[4][2];
#pragma unroll
            for (int mt = 0; mt < 2; mt++) {
                int base = (wm * 32 + mt * 16 + lr) * 40 + kk + lq;
                ah[mt][0] = *(const uint32_t*)(sah + base);
                ah[mt][1] = *(const uint32_t*)(sah + base + 320);
                ah[mt][2] = *(const uint32_t*)(sah + base + 8);
                ah[mt][3] = *(const uint32_t*)(sah + base + 328);
                al[mt][0] = *(const uint32_t*)(sal + base);
                al[mt][1] = *(const uint32_t*)(sal + base + 320);
                al[mt][2] = *(const uint32_t*)(sal + base + 8);
                al[mt][3] = *(const uint32_t*)(sal + base + 328);
            }
#pragma unroll
            for (int nt = 0; nt < 4; nt++) {
                int base = (wn * 32 + nt * 8 + lr) * 40 + kk + lq;
                bh[nt][0] = *(const uint32_t*)(sbh + base);
                bh[nt][1] = *(const uint32_t*)(sbh + base + 8);
                bl[nt][0] = *(const uint32_t*)(sbl + base);
                bl[nt][1] = *(const uint32_t*)(sbl + base + 8);
            }
#pragma unroll
            for (int mt = 0; mt < 2; mt++)
#pragma unroll
                for (int nt = 0; nt < 4; nt++) {
                    MMA16816(c[mt][nt], ah[mt], bh[nt]);   // hi*hi
                    MMA16816(c[mt][nt], ah[mt], bl[nt]);   // hi*lo
                    MMA16816(c[mt][nt], al[mt], bh[nt]);   // lo*hi
                }
        }
    };

    prefetch(0);
    store_stage(0);
    __syncthreads();
#pragma unroll 1
    for (int s = 1; s < NSTAGE; s++) {
        prefetch(s);
        compute_stage((s - 1) & 1);
        __syncthreads();
        store_stage(s & 1);
        __syncthreads();
    }
    compute_stage((NSTAGE - 1) & 1);

    // ---- recurrence ----
    const float beta = fminf(fmaxf(__ldg(beta_p), 0.0f), 1.0f);
    float thv[8];
#pragma unroll
    for (int j = 0; j < 8; j++) {
        int col = wn * 32 + (j >> 1) * 8 + lq + (j & 1);
        thv[j] = sTH[col];
    }

    float rowacc[4];
#pragma unroll
    for (int r = 0; r < 4; r++) rowacc[r] = 0.0f;

#pragma unroll 1
    for (int mt = 0; mt < 2; mt++) {
        float x1[16], x1m[16], m[16];
        int cnt[16];
        bool p[16];
#pragma unroll
        for (int e = 0; e < 16; e++) {
            const int nt = e >> 2, rr = (e >> 1) & 1, cc = e & 1;
            const int j = nt * 2 + cc;
            const int col = wn * 32 + nt * 8 + lq + cc;
            x1[e]  = c[mt][nt][rr * 2 + cc] + sB1[col];
            x1m[e] = x1[e] - thv[j];
            m[e]   = 0.0f;
            cnt[e] = 0;
            p[e]   = (0.0f > thv[j]);          // reset from mem0 = 0
        }
#pragma unroll 1
        for (int t = 0; t < NSTEPS; t++) {
#pragma unroll
            for (int e = 0; e < 16; e++) {
                const int j = (e >> 2) * 2 + (e & 1);
                float inp = p[e] ? x1m[e] : x1[e];
                m[e] = fmaf(beta, m[e], inp);
                p[e] = m[e] > thv[j];
                cnt[e] += p[e];
            }
        }
#pragma unroll
        for (int e = 0; e < 16; e++) {
            const int nt = e >> 2, rr = (e >> 1) & 1, cc = e & 1;
            const int col = wn * 32 + nt * 8 + lq + cc;
            rowacc[mt * 2 + rr] = fmaf((float)cnt[e], sW2[col], rowacc[mt * 2 + rr]);
        }
    }

    // ---- reduce across the 4 lanes sharing each row, then atomicAdd ----
#pragma unroll
    for (int r = 0; r < 4; r++) {
        float v = rowacc[r];
        v += __shfl_xor_sync(0xffffffffu, v, 1);
        v += __shfl_xor_sync(0xffffffffu, v, 2);
        if ((l & 3) == 0) {
            const int mt = r >> 1, rr = r & 1;
            atomicAdd(&out[b0 + wm * 32 + mt * 16 + lr + rr * 8], v);
        }
    }
}

extern "C" void kernel_launch(void* const* d_in, const int* in_sizes, int n_in,
                              void* d_out, int out_size) {
    const float* x    = (const float*)d_in[0];
    const float* W1   = (const float*)d_in[1];
    const float* b1   = (const float*)d_in[2];
    const float* W2   = (const float*)d_in[3];
    const float* b2   = (const float*)d_in[4];
    const float* beta = (const float*)d_in[5];
    const float* thr  = (const float*)d_in[6];
    float* out = (float*)d_out;

    const int B = in_sizes[0] / NIc;  // 32768

    // pre-pass: split x and W1 into fp16 hi/lo
    __half *xhi, *xlo, *whi, *wlo;
    cudaGetSymbolAddress((void**)&xhi, g_xhi);
    cudaGetSymbolAddress((void**)&xlo, g_xlo);
    cudaGetSymbolAddress((void**)&whi, g_whi);
    cudaGetSymbolAddress((void**)&wlo, g_wlo);

    const int nx4 = B * NIc / 4;
    const int nw4 = NHc * NIc / 4;
    cvt_kernel<<<(nx4 + 255) / 256, 256>>>(x, xhi, xlo, nx4);
    cvt_kernel<<<(nw4 + 255) / 256, 256>>>(W1, whi, wlo, nw4);

    init_out_kernel<<<(B + 255) / 256, 256>>>(out, b2, B);

    cudaFuncSetAttribute(snn_mma_kernel,
                         cudaFuncAttributeMaxDynamicSharedMemorySize, SMEM_TOTAL);

    dim3 grid(NHc / BN, B / BM);  // (16, 256): h fastest -> x tile reuse in L2
    snn_mma_kernel<<<grid, 256, SMEM_TOTAL>>>(b1, W2, beta, thr, out);
}

// round 4
// speedup vs baseline: 1.1953x; 1.0677x over previous
#include <cuda_runtime.h>
#include <cuda_fp16.h>
#include <cstdint>

// LeakySNN: x1 = x@W1^T + b1 via fp16 2-term-split mma.sync (3 products, f32 accum),
// ldmatrix fragment loads, 25-step LIF recurrence (FSET/FADD/2xFFMA), spk.W2 -> atomicAdd.
// Shapes fixed: B=32768, NI=256, NH=1024, NO=1, NUM_STEPS=25.

#define NIc     256
#define NHc     1024
#define BTOT    32768
#define NSTEPS  25
#define BM      128
#define BN      64
#define BK      32
#define NSTAGE  (NIc / BK)   // 8

// smem stage layout (bytes within a stage); rows stride 80B (40 halves)
#define A_HI_B   0
#define A_LO_B   10240
#define B_HI_B   20480
#define B_LO_B   25600
#define STG_B    30720
#define SMEM_CONST 1024
#define SMEM_TOTAL (SMEM_CONST + 2 * STG_B)   // 62464 bytes

__device__ __half g_xhi[(size_t)BTOT * NIc];
__device__ __half g_xlo[(size_t)BTOT * NIc];
__device__ __half g_whi[(size_t)NHc * NIc];
__device__ __half g_wlo[(size_t)NHc * NIc];

__global__ void cvt_kernel(const float* __restrict__ src,
                           __half* __restrict__ hi, __half* __restrict__ lo,
                           int n4) {
    int i = blockIdx.x * blockDim.x + threadIdx.x;
    if (i >= n4) return;
    float4 v = *((const float4*)src + i);
    __half h0 = __float2half_rn(v.x), h1 = __float2half_rn(v.y);
    __half h2 = __float2half_rn(v.z), h3 = __float2half_rn(v.w);
    __half l0 = __float2half_rn(v.x - __half2float(h0));
    __half l1 = __float2half_rn(v.y - __half2float(h1));
    __half l2 = __float2half_rn(v.z - __half2float(h2));
    __half l3 = __float2half_rn(v.w - __half2float(h3));
    __half2* ph = (__half2*)(hi + (size_t)i * 4);
    __half2* pl = (__half2*)(lo + (size_t)i * 4);
    ph[0] = __halves2half2(h0, h1); ph[1] = __halves2half2(h2, h3);
    pl[0] = __halves2half2(l0, l1); pl[1] = __halves2half2(l2, l3);
}

__global__ void init_out_kernel(float* __restrict__ out,
                                const float* __restrict__ b2, int n) {
    int i = blockIdx.x * blockDim.x + threadIdx.x;
    if (i < n) out[i] = b2[0];
}

__device__ __forceinline__ uint32_t smem_u32(const void* p) {
    uint32_t a;
    asm("{ .reg .u64 t; cvta.to.shared.u64 t, %1; cvt.u32.u64 %0, t; }" : "=r"(a) : "l"(p));
    return a;
}

#define MMA16816(C, A, B) \
    asm volatile("mma.sync.aligned.m16n8k16.row.col.f32.f16.f16.f32 " \
        "{%0,%1,%2,%3}, {%4,%5,%6,%7}, {%8,%9}, {%0,%1,%2,%3};" \
        : "+f"((C)[0]), "+f"((C)[1]), "+f"((C)[2]), "+f"((C)[3]) \
        : "r"((A)[0]), "r"((A)[1]), "r"((A)[2]), "r"((A)[3]), \
          "r"((B)[0]), "r"((B)[1]))

#define LDMATRIX_X4(R, addr) \
    asm volatile("ldmatrix.sync.aligned.m8n8.x4.shared.b16 {%0,%1,%2,%3}, [%4];" \
        : "=r"((R)[0]), "=r"((R)[1]), "=r"((R)[2]), "=r"((R)[3]) : "r"(addr))

__global__ void __launch_bounds__(256, 2)
snn_mma_kernel(const float* __restrict__ b1,
               const float* __restrict__ W2,
               const float* __restrict__ beta_p,
               const float* __restrict__ thr,
               float* __restrict__ out) {
    extern __shared__ __align__(16) char smem[];
    float* sB1 = (float*)smem;
    float* sTH = sB1 + 64;
    float* sW2 = sTH + 64;
    __half* stg = (__half*)(smem + SMEM_CONST);

    const int tid = threadIdx.x;
    const int l   = tid & 31;
    const int wid = tid >> 5;
    const int wm  = wid & 3;        // 4 warps along M (32 rows each)
    const int wn  = wid >> 2;       // 2 warps along N (32 cols each)
    const int h0  = blockIdx.x * BN;
    const int b0  = blockIdx.y * BM;

    if (tid < 64) {
        sB1[tid] = b1[h0 + tid];
        sTH[tid] = thr[h0 + tid];
        sW2[tid] = W2[h0 + tid];
    }

    // ---- gmem->smem staging ----
    const int rowA = tid >> 1, caOff = (tid & 1) * 16;
    const int rowB = tid >> 2, cbOff = (tid & 3) * 8;
    const __half* pxh = g_xhi + (size_t)(b0 + rowA) * NIc + caOff;
    const __half* pxl = g_xlo + (size_t)(b0 + rowA) * NIc + caOff;
    const __half* pwh = g_whi + (size_t)(h0 + rowB) * NIc + cbOff;
    const __half* pwl = g_wlo + (size_t)(h0 + rowB) * NIc + cbOff;
    const int smA = rowA * 40 + caOff;   // half-index
    const int smB = rowB * 40 + cbOff;

    uint4 rah0, rah1, ral0, ral1, rbh, rbl;
    auto prefetch = [&](int s) {
        rah0 = *(const uint4*)(pxh + s * BK);
        rah1 = *(const uint4*)(pxh + s * BK + 8);
        ral0 = *(const uint4*)(pxl + s * BK);
        ral1 = *(const uint4*)(pxl + s * BK + 8);
        rbh  = *(const uint4*)(pwh + s * BK);
        rbl  = *(const uint4*)(pwl + s * BK);
    };
    auto store_stage = [&](int buf) {
        __half* t = stg + buf * (STG_B / 2);
        *(uint4*)(t + (A_HI_B / 2) + smA)     = rah0;
        *(uint4*)(t + (A_HI_B / 2) + smA + 8) = rah1;
        *(uint4*)(t + (A_LO_B / 2) + smA)     = ral0;
        *(uint4*)(t + (A_LO_B / 2) + smA + 8) = ral1;
        *(uint4*)(t + (B_HI_B / 2) + smB)     = rbh;
        *(uint4*)(t + (B_LO_B / 2) + smB)     = rbl;
    };

    // ---- ldmatrix addresses (bytes, stage-0 base) ----
    const uint32_t stg0 = smem_u32(stg);
    const int mrow = l & 7, msel = l >> 3;
    // A: matrix m: row = (m%2)*8 + mrow, k = (m/2)*8
    uint32_t aHi[2], aLo[2];
#pragma unroll
    for (int mt = 0; mt < 2; mt++) {
        int row = wm * 32 + mt * 16 + (msel & 1) * 8 + mrow;
        int kof = (msel >> 1) * 8;
        aHi[mt] = stg0 + A_HI_B + row * 80 + kof * 2;
        aLo[mt] = stg0 + A_LO_B + row * 80 + kof * 2;
    }
    // B: matrix m: n = (m/2)*8 + mrow, k = (m%2)*8 ; pair p covers nt {2p, 2p+1}
    uint32_t bHi[2], bLo[2];
#pragma unroll
    for (int p = 0; p < 2; p++) {
        int n   = wn * 32 + p * 16 + (msel >> 1) * 8 + mrow;
        int kof = (msel & 1) * 8;
        bHi[p] = stg0 + B_HI_B + n * 80 + kof * 2;
        bLo[p] = stg0 + B_LO_B + n * 80 + kof * 2;
    }

    float c[2][4][4];
#pragma unroll
    for (int mt = 0; mt < 2; mt++)
#pragma unroll
        for (int nt = 0; nt < 4; nt++)
#pragma unroll
            for (int r = 0; r < 4; r++) c[mt][nt][r] = 0.0f;

    auto compute_stage = [&](int buf) {
        const uint32_t so = (uint32_t)buf * STG_B;
#pragma unroll
        for (int ks = 0; ks < 2; ks++) {
            const uint32_t ko = so + ks * 32;   // 16 halves = 32 bytes
            uint32_t ah[2][4], al[2][4], bh[2][4], bl[2][4];
#pragma unroll
            for (int mt = 0; mt < 2; mt++) {
                LDMATRIX_X4(ah[mt], aHi[mt] + ko);
                LDMATRIX_X4(al[mt], aLo[mt] + ko);
            }
#pragma unroll
            for (int p = 0; p < 2; p++) {
                LDMATRIX_X4(bh[p], bHi[p] + ko);
                LDMATRIX_X4(bl[p], bLo[p] + ko);
            }
#pragma unroll
            for (int mt = 0; mt < 2; mt++)
#pragma unroll
                for (int nt = 0; nt < 4; nt++) {
                    const int p = nt >> 1, q = (nt & 1) * 2;
                    MMA16816(c[mt][nt], ah[mt], &bh[p][q]);   // hi*hi
                    MMA16816(c[mt][nt], ah[mt], &bl[p][q]);   // hi*lo
                    MMA16816(c[mt][nt], al[mt], &bh[p][q]);   // lo*hi
                }
        }
    };

    prefetch(0);
    store_stage(0);
    __syncthreads();
#pragma unroll 1
    for (int s = 1; s < NSTAGE; s++) {
        prefetch(s);
        compute_stage((s - 1) & 1);
        __syncthreads();
        store_stage(s & 1);
        __syncthreads();
    }
    compute_stage((NSTAGE - 1) & 1);

    // ---- recurrence: s=set.gt(m,thr); cnt+=s; m=fma(beta,m,fma(s,-thr,x1)) ----
    const float beta = fminf(fmaxf(__ldg(beta_p), 0.0f), 1.0f);
    const int lr = l >> 2;          // 0..7
    const int lq = (l & 3) * 2;     // 0,2,4,6

    float thv[8], nthv[8];
#pragma unroll
    for (int j = 0; j < 8; j++) {
        int col = wn * 32 + (j >> 1) * 8 + lq + (j & 1);
        thv[j]  = sTH[col];
        nthv[j] = -thv[j];
    }

    float rowacc[4];
#pragma unroll
    for (int r = 0; r < 4; r++) rowacc[r] = 0.0f;

#pragma unroll 1
    for (int mt = 0; mt < 2; mt++) {
        float x1[16], m[16], cnt[16];
#pragma unroll
        for (int e = 0; e < 16; e++) {
            const int nt = e >> 2, rr = (e >> 1) & 1, cc = e & 1;
            const int col = wn * 32 + nt * 8 + lq + cc;
            x1[e]  = c[mt][nt][rr * 2 + cc] + sB1[col];
            cnt[e] = 0.0f;
        }
        // step 1 from mem0 = 0: reset = H(0 - thr) -> thr>0 => no reset; m1 = x1
#pragma unroll
        for (int e = 0; e < 16; e++) {
            const int j = (e >> 2) * 2 + (e & 1);
            float s0;  // reset from mem0=0: 1.0 iff 0 > thr
            asm("set.gt.f32.f32 %0, %1, %2;" : "=f"(s0) : "f"(0.0f), "f"(thv[j]));
            m[e] = fmaf(s0, nthv[j], x1[e]);   // beta*0 + (x1 - s*thr)
        }
#pragma unroll 5
        for (int t = 1; t < NSTEPS; t++) {
#pragma unroll
            for (int e = 0; e < 16; e++) {
                const int j = (e >> 2) * 2 + (e & 1);
                float s;
                asm("set.gt.f32.f32 %0, %1, %2;" : "=f"(s) : "f"(m[e]), "f"(thv[j]));
                cnt[e] += s;
                m[e] = fmaf(beta, m[e], fmaf(s, nthv[j], x1[e]));
            }
        }
        // final spike after last membrane update
#pragma unroll
        for (int e = 0; e < 16; e++) {
            const int j = (e >> 2) * 2 + (e & 1);
            float s;
            asm("set.gt.f32.f32 %0, %1, %2;" : "=f"(s) : "f"(m[e]), "f"(thv[j]));
            cnt[e] += s;
        }
#pragma unroll
        for (int e = 0; e < 16; e++) {
            const int nt = e >> 2, rr = (e >> 1) & 1, cc = e & 1;
            const int col = wn * 32 + nt * 8 + lq + cc;
            rowacc[mt * 2 + rr] = fmaf(cnt[e], sW2[col], rowacc[mt * 2 + rr]);
        }
    }

#pragma unroll
    for (int r = 0; r < 4; r++) {
        float v = rowacc[r];
        v += __shfl_xor_sync(0xffffffffu, v, 1);
        v += __shfl_xor_sync(0xffffffffu, v, 2);
        if ((l & 3) == 0) {
            const int mt = r >> 1, rr = r & 1;
            atomicAdd(&out[b0 + wm * 32 + mt * 16 + lr + rr * 8], v);
        }
    }
}

extern "C" void kernel_launch(void* const* d_in, const int* in_sizes, int n_in,
                              void* d_out, int out_size) {
    const float* x    = (const float*)d_in[0];
    const float* W1   = (const float*)d_in[1];
    const float* b1   = (const float*)d_in[2];
    const float* W2   = (const float*)d_in[3];
    const float* b2   = (const float*)d_in[4];
    const float* beta = (const float*)d_in[5];
    const float* thr  = (const float*)d_in[6];
    float* out = (float*)d_out;

    const int B = in_sizes[0] / NIc;  // 32768

    __half *xhi, *xlo, *whi, *wlo;
    cudaGetSymbolAddress((void**)&xhi, g_xhi);
    cudaGetSymbolAddress((void**)&xlo, g_xlo);
    cudaGetSymbolAddress((void**)&whi, g_whi);
    cudaGetSymbolAddress((void**)&wlo, g_wlo);

    const int nx4 = B * NIc / 4;
    const int nw4 = NHc * NIc / 4;
    cvt_kernel<<<(nx4 + 255) / 256, 256>>>(x, xhi, xlo, nx4);
    cvt_kernel<<<(nw4 + 255) / 256, 256>>>(W1, whi, wlo, nw4);

    init_out_kernel<<<(B + 255) / 256, 256>>>(out, b2, B);

    cudaFuncSetAttribute(snn_mma_kernel,
                         cudaFuncAttributeMaxDynamicSharedMemorySize, SMEM_TOTAL);

    dim3 grid(NHc / BN, B / BM);  // h fastest -> x tile reuse in L2
    snn_mma_kernel<<<grid, 256, SMEM_TOTAL>>>(b1, W2, beta, thr, out);
}

// round 5
// speedup vs baseline: 1.2424x; 1.0394x over previous
#include <cuda_runtime.h>
#include <cuda_fp16.h>
#include <cstdint>

// LeakySNN: x1 = x@W1^T + b1 via fp16 2-term-split mma.sync (3 products, f32 accum),
// cp.async 3-stage pipeline (1 barrier/stage), ldmatrix frags, product-major MMA order,
// 25-step LIF recurrence (FSET/FADD/2xFFMA), spk.W2 -> atomicAdd.
// Shapes fixed: B=32768, NI=256, NH=1024, NO=1, NUM_STEPS=25.

#define NIc     256
#define NHc     1024
#define BTOT    32768
#define NSTEPS  25
#define BM      128
#define BN      64
#define BK      32
#define NSTAGE  (NIc / BK)   // 8
#define PIPE    3            // smem pipeline depth

// smem stage layout (bytes within a stage); rows stride 80B (40 halves)
#define A_HI_B   0
#define A_LO_B   10240
#define B_HI_B   20480
#define B_LO_B   25600
#define STG_B    30720
#define SMEM_CONST 1024
#define SMEM_TOTAL (SMEM_CONST + PIPE * STG_B)   // 93184 bytes -> 2 blocks/SM

__device__ __half g_xhi[(size_t)BTOT * NIc];
__device__ __half g_xlo[(size_t)BTOT * NIc];
__device__ __half g_whi[(size_t)NHc * NIc];
__device__ __half g_wlo[(size_t)NHc * NIc];

__global__ void cvt_kernel(const float* __restrict__ src,
                           __half* __restrict__ hi, __half* __restrict__ lo,
                           int n4) {
    int i = blockIdx.x * blockDim.x + threadIdx.x;
    if (i >= n4) return;
    float4 v = *((const float4*)src + i);
    __half h0 = __float2half_rn(v.x), h1 = __float2half_rn(v.y);
    __half h2 = __float2half_rn(v.z), h3 = __float2half_rn(v.w);
    __half l0 = __float2half_rn(v.x - __half2float(h0));
    __half l1 = __float2half_rn(v.y - __half2float(h1));
    __half l2 = __float2half_rn(v.z - __half2float(h2));
    __half l3 = __float2half_rn(v.w - __half2float(h3));
    __half2* ph = (__half2*)(hi + (size_t)i * 4);
    __half2* pl = (__half2*)(lo + (size_t)i * 4);
    ph[0] = __halves2half2(h0, h1); ph[1] = __halves2half2(h2, h3);
    pl[0] = __halves2half2(l0, l1); pl[1] = __halves2half2(l2, l3);
}

__global__ void init_out_kernel(float* __restrict__ out,
                                const float* __restrict__ b2, int n) {
    int i = blockIdx.x * blockDim.x + threadIdx.x;
    if (i < n) out[i] = b2[0];
}

__device__ __forceinline__ uint32_t smem_u32(const void* p) {
    uint32_t a;
    asm("{ .reg .u64 t; cvta.to.shared.u64 t, %1; cvt.u32.u64 %0, t; }" : "=r"(a) : "l"(p));
    return a;
}

__device__ __forceinline__ void cpasync16(uint32_t dst, const void* src) {
    asm volatile("cp.async.ca.shared.global [%0], [%1], 16;"
                 :: "r"(dst), "l"(__cvta_generic_to_global(src)) : "memory");
}
#define CP_COMMIT() asm volatile("cp.async.commit_group;" ::: "memory")
#define CP_WAIT(n)  asm volatile("cp.async.wait_group %0;" :: "n"(n) : "memory")

#define MMA16816(C, A, B) \
    asm volatile("mma.sync.aligned.m16n8k16.row.col.f32.f16.f16.f32 " \
        "{%0,%1,%2,%3}, {%4,%5,%6,%7}, {%8,%9}, {%0,%1,%2,%3};" \
        : "+f"((C)[0]), "+f"((C)[1]), "+f"((C)[2]), "+f"((C)[3]) \
        : "r"((A)[0]), "r"((A)[1]), "r"((A)[2]), "r"((A)[3]), \
          "r"((B)[0]), "r"((B)[1]))

#define LDMATRIX_X4(R, addr) \
    asm volatile("ldmatrix.sync.aligned.m8n8.x4.shared.b16 {%0,%1,%2,%3}, [%4];" \
        : "=r"((R)[0]), "=r"((R)[1]), "=r"((R)[2]), "=r"((R)[3]) : "r"(addr))

__global__ void __launch_bounds__(256, 2)
snn_mma_kernel(const float* __restrict__ b1,
               const float* __restrict__ W2,
               const float* __restrict__ beta_p,
               const float* __restrict__ thr,
               float* __restrict__ out) {
    extern __shared__ __align__(16) char smem[];
    float* sB1 = (float*)smem;
    float* sTH = sB1 + 64;
    float* sW2 = sTH + 64;
    __half* stg = (__half*)(smem + SMEM_CONST);

    const int tid = threadIdx.x;
    const int l   = tid & 31;
    const int wid = tid >> 5;
    const int wm  = wid & 3;        // 4 warps along M (32 rows each)
    const int wn  = wid >> 2;       // 2 warps along N (32 cols each)
    const int h0  = blockIdx.x * BN;
    const int b0  = blockIdx.y * BM;

    if (tid < 64) {
        sB1[tid] = b1[h0 + tid];
        sTH[tid] = thr[h0 + tid];
        sW2[tid] = W2[h0 + tid];
    }

    // ---- gmem->smem async staging ----
    const int rowA = tid >> 1, caOff = (tid & 1) * 16;
    const int rowB = tid >> 2, cbOff = (tid & 3) * 8;
    const __half* pxh = g_xhi + (size_t)(b0 + rowA) * NIc + caOff;
    const __half* pxl = g_xlo + (size_t)(b0 + rowA) * NIc + caOff;
    const __half* pwh = g_whi + (size_t)(h0 + rowB) * NIc + cbOff;
    const __half* pwl = g_wlo + (size_t)(h0 + rowB) * NIc + cbOff;
    const uint32_t stg0 = smem_u32(stg);
    const uint32_t smA = stg0 + (rowA * 40 + caOff) * 2;   // bytes
    const uint32_t smB = stg0 + (rowB * 40 + cbOff) * 2;

    auto issue_copy = [&](int s, int buf) {
        const uint32_t so = (uint32_t)buf * STG_B;
        cpasync16(smA + A_HI_B + so,      pxh + s * BK);
        cpasync16(smA + A_HI_B + so + 16, pxh + s * BK + 8);
        cpasync16(smA + A_LO_B + so,      pxl + s * BK);
        cpasync16(smA + A_LO_B + so + 16, pxl + s * BK + 8);
        cpasync16(smB + B_HI_B + so,      pwh + s * BK);
        cpasync16(smB + B_LO_B + so,      pwl + s * BK);
        CP_COMMIT();
    };

    // ---- ldmatrix addresses (bytes, stage-0 base) ----
    const int mrow = l & 7, msel = l >> 3;
    uint32_t aHi[2], aLo[2];
#pragma unroll
    for (int mt = 0; mt < 2; mt++) {
        int row = wm * 32 + mt * 16 + (msel & 1) * 8 + mrow;
        int kof = (msel >> 1) * 8;
        aHi[mt] = stg0 + A_HI_B + row * 80 + kof * 2;
        aLo[mt] = stg0 + A_LO_B + row * 80 + kof * 2;
    }
    uint32_t bHi[2], bLo[2];
#pragma unroll
    for (int p = 0; p < 2; p++) {
        int n   = wn * 32 + p * 16 + (msel >> 1) * 8 + mrow;
        int kof = (msel & 1) * 8;
        bHi[p] = stg0 + B_HI_B + n * 80 + kof * 2;
        bLo[p] = stg0 + B_LO_B + n * 80 + kof * 2;
    }

    float c[2][4][4];
#pragma unroll
    for (int mt = 0; mt < 2; mt++)
#pragma unroll
        for (int nt = 0; nt < 4; nt++)
#pragma unroll
            for (int r = 0; r < 4; r++) c[mt][nt][r] = 0.0f;

    auto compute_stage = [&](int buf) {
        const uint32_t so = (uint32_t)buf * STG_B;
#pragma unroll
        for (int ks = 0; ks < 2; ks++) {
            const uint32_t ko = so + ks * 32;   // 16 halves = 32 bytes
            uint32_t ah[2][4], al[2][4], bh[2][4], bl[2][4];
#pragma unroll
            for (int mt = 0; mt < 2; mt++) {
                LDMATRIX_X4(ah[mt], aHi[mt] + ko);
                LDMATRIX_X4(al[mt], aLo[mt] + ko);
            }
#pragma unroll
            for (int p = 0; p < 2; p++) {
                LDMATRIX_X4(bh[p], bHi[p] + ko);
                LDMATRIX_X4(bl[p], bLo[p] + ko);
            }
            // product-major order: 8 independent accumulators between RAW reuses
#pragma unroll
            for (int mt = 0; mt < 2; mt++)
#pragma unroll
                for (int nt = 0; nt < 4; nt++)
                    MMA16816(c[mt][nt], ah[mt], &bh[nt >> 1][(nt & 1) * 2]);
#pragma unroll
            for (int mt = 0; mt < 2; mt++)
#pragma unroll
                for (int nt = 0; nt < 4; nt++)
                    MMA16816(c[mt][nt], ah[mt], &bl[nt >> 1][(nt & 1) * 2]);
#pragma unroll
            for (int mt = 0; mt < 2; mt++)
#pragma unroll
                for (int nt = 0; nt < 4; nt++)
                    MMA16816(c[mt][nt], al[mt], &bh[nt >> 1][(nt & 1) * 2]);
        }
    };

    // ---- pipelined mainloop: 1 barrier per stage ----
    issue_copy(0, 0);
    issue_copy(1, 1);

#pragma unroll 1
    for (int s = 0; s < NSTAGE; s++) {
        if (s == NSTAGE - 1) { CP_WAIT(0); } else { CP_WAIT(1); }
        __syncthreads();   // stage s fully in smem; all warps done with stage s-1
        if (s + 2 < NSTAGE) issue_copy(s + 2, (s + 2) % PIPE);
        compute_stage(s % PIPE);
    }

    // ---- recurrence: s=set.gt(m,thr); cnt+=s; m=fma(beta,m,fma(s,-thr,x1)) ----
    const float beta = fminf(fmaxf(__ldg(beta_p), 0.0f), 1.0f);
    const int lr = l >> 2;          // 0..7
    const int lq = (l & 3) * 2;     // 0,2,4,6

    float thv[8], nthv[8];
#pragma unroll
    for (int j = 0; j < 8; j++) {
        int col = wn * 32 + (j >> 1) * 8 + lq + (j & 1);
        thv[j]  = sTH[col];
        nthv[j] = -thv[j];
    }

    float rowacc[4];
#pragma unroll
    for (int r = 0; r < 4; r++) rowacc[r] = 0.0f;

#pragma unroll 1
    for (int mt = 0; mt < 2; mt++) {
        float x1[16], m[16], cnt[16];
#pragma unroll
        for (int e = 0; e < 16; e++) {
            const int nt = e >> 2, rr = (e >> 1) & 1, cc = e & 1;
            const int col = wn * 32 + nt * 8 + lq + cc;
            x1[e]  = c[mt][nt][rr * 2 + cc] + sB1[col];
            cnt[e] = 0.0f;
        }
        // step 1 from mem0 = 0: reset = H(0 - thr)
#pragma unroll
        for (int e = 0; e < 16; e++) {
            const int j = (e >> 2) * 2 + (e & 1);
            float s0;
            asm("set.gt.f32.f32 %0, %1, %2;" : "=f"(s0) : "f"(0.0f), "f"(thv[j]));
            m[e] = fmaf(s0, nthv[j], x1[e]);
        }
#pragma unroll 5
        for (int t = 1; t < NSTEPS; t++) {
#pragma unroll
            for (int e = 0; e < 16; e++) {
                const int j = (e >> 2) * 2 + (e & 1);
                float s;
                asm("set.gt.f32.f32 %0, %1, %2;" : "=f"(s) : "f"(m[e]), "f"(thv[j]));
                cnt[e] += s;
                m[e] = fmaf(beta, m[e], fmaf(s, nthv[j], x1[e]));
            }
        }
#pragma unroll
        for (int e = 0; e < 16; e++) {
            const int j = (e >> 2) * 2 + (e & 1);
            float s;
            asm("set.gt.f32.f32 %0, %1, %2;" : "=f"(s) : "f"(m[e]), "f"(thv[j]));
            cnt[e] += s;
        }
#pragma unroll
        for (int e = 0; e < 16; e++) {
            const int nt = e >> 2, rr = (e >> 1) & 1, cc = e & 1;
            const int col = wn * 32 + nt * 8 + lq + cc;
            rowacc[mt * 2 + rr] = fmaf(cnt[e], sW2[col], rowacc[mt * 2 + rr]);
        }
    }

#pragma unroll
    for (int r = 0; r < 4; r++) {
        float v = rowacc[r];
        v += __shfl_xor_sync(0xffffffffu, v, 1);
        v += __shfl_xor_sync(0xffffffffu, v, 2);
        if ((l & 3) == 0) {
            const int mt = r >> 1, rr = r & 1;
            atomicAdd(&out[b0 + wm * 32 + mt * 16 + lr + rr * 8], v);
        }
    }
}

extern "C" void kernel_launch(void* const* d_in, const int* in_sizes, int n_in,
                              void* d_out, int out_size) {
    const float* x    = (const float*)d_in[0];
    const float* W1   = (const float*)d_in[1];
    const float* b1   = (const float*)d_in[2];
    const float* W2   = (const float*)d_in[3];
    const float* b2   = (const float*)d_in[4];
    const float* beta = (const float*)d_in[5];
    const float* thr  = (const float*)d_in[6];
    float* out = (float*)d_out;

    const int B = in_sizes[0] / NIc;  // 32768

    __half *xhi, *xlo, *whi, *wlo;
    cudaGetSymbolAddress((void**)&xhi, g_xhi);
    cudaGetSymbolAddress((void**)&xlo, g_xlo);
    cudaGetSymbolAddress((void**)&whi, g_whi);
    cudaGetSymbolAddress((void**)&wlo, g_wlo);

    const int nx4 = B * NIc / 4;
    const int nw4 = NHc * NIc / 4;
    cvt_kernel<<<(nx4 + 255) / 256, 256>>>(x, xhi, xlo, nx4);
    cvt_kernel<<<(nw4 + 255) / 256, 256>>>(W1, whi, wlo, nw4);

    init_out_kernel<<<(B + 255) / 256, 256>>>(out, b2, B);

    cudaFuncSetAttribute(snn_mma_kernel,
                         cudaFuncAttributeMaxDynamicSharedMemorySize, SMEM_TOTAL);

    dim3 grid(NHc / BN, B / BM);  // h fastest -> x tile reuse in L2
    snn_mma_kernel<<<grid, 256, SMEM_TOTAL>>>(b1, W2, beta, thr, out);
}

// round 6
// speedup vs baseline: 1.4221x; 1.1446x over previous
#include <cuda_runtime.h>
#include <cuda_fp16.h>
#include <cstdint>

// LeakySNN, de-fused:
//  K1 cvt: x,W1 -> fp16 hi/lo split arrays
//  K2 gemm: x1 = x@W1^T + b1 via fp16 3-product mma.sync -> g_x1 (f32, gmem)
//  K3 lif:  25-step recurrence on g_x1, spk.W2 -> atomicAdd(out)  [full occupancy]
// Shapes fixed: B=32768, NI=256, NH=1024, NO=1, NUM_STEPS=25.

#define NIc     256
#define NHc     1024
#define BTOT    32768
#define NSTEPS  25
#define BM      128
#define BN      64
#define BK      32
#define NSTAGE  (NIc / BK)   // 8
#define PIPE    3

#define A_HI_B   0
#define A_LO_B   10240
#define B_HI_B   20480
#define B_LO_B   25600
#define STG_B    30720
#define SMEM_TOTAL (PIPE * STG_B)   // 92160

__device__ __half g_xhi[(size_t)BTOT * NIc];
__device__ __half g_xlo[(size_t)BTOT * NIc];
__device__ __half g_whi[(size_t)NHc * NIc];
__device__ __half g_wlo[(size_t)NHc * NIc];
__device__ float  g_x1[(size_t)BTOT * NHc];   // 128 MB scratch

__global__ void cvt_kernel(const float* __restrict__ src,
                           __half* __restrict__ hi, __half* __restrict__ lo,
                           int n4) {
    int i = blockIdx.x * blockDim.x + threadIdx.x;
    if (i >= n4) return;
    float4 v = *((const float4*)src + i);
    __half h0 = __float2half_rn(v.x), h1 = __float2half_rn(v.y);
    __half h2 = __float2half_rn(v.z), h3 = __float2half_rn(v.w);
    __half l0 = __float2half_rn(v.x - __half2float(h0));
    __half l1 = __float2half_rn(v.y - __half2float(h1));
    __half l2 = __float2half_rn(v.z - __half2float(h2));
    __half l3 = __float2half_rn(v.w - __half2float(h3));
    __half2* ph = (__half2*)(hi + (size_t)i * 4);
    __half2* pl = (__half2*)(lo + (size_t)i * 4);
    ph[0] = __halves2half2(h0, h1); ph[1] = __halves2half2(h2, h3);
    pl[0] = __halves2half2(l0, l1); pl[1] = __halves2half2(l2, l3);
}

__global__ void init_out_kernel(float* __restrict__ out,
                                const float* __restrict__ b2, int n) {
    int i = blockIdx.x * blockDim.x + threadIdx.x;
    if (i < n) out[i] = b2[0];
}

__device__ __forceinline__ uint32_t smem_u32(const void* p) {
    uint32_t a;
    asm("{ .reg .u64 t; cvta.to.shared.u64 t, %1; cvt.u32.u64 %0, t; }" : "=r"(a) : "l"(p));
    return a;
}

__device__ __forceinline__ void cpasync16(uint32_t dst, const void* src) {
    asm volatile("cp.async.ca.shared.global [%0], [%1], 16;"
                 :: "r"(dst), "l"(__cvta_generic_to_global(src)) : "memory");
}
#define CP_COMMIT() asm volatile("cp.async.commit_group;" ::: "memory")
#define CP_WAIT(n)  asm volatile("cp.async.wait_group %0;" :: "n"(n) : "memory")

#define MMA16816(C, A, B) \
    asm volatile("mma.sync.aligned.m16n8k16.row.col.f32.f16.f16.f32 " \
        "{%0,%1,%2,%3}, {%4,%5,%6,%7}, {%8,%9}, {%0,%1,%2,%3};" \
        : "+f"((C)[0]), "+f"((C)[1]), "+f"((C)[2]), "+f"((C)[3]) \
        : "r"((A)[0]), "r"((A)[1]), "r"((A)[2]), "r"((A)[3]), \
          "r"((B)[0]), "r"((B)[1]))

#define LDMATRIX_X4(R, addr) \
    asm volatile("ldmatrix.sync.aligned.m8n8.x4.shared.b16 {%0,%1,%2,%3}, [%4];" \
        : "=r"((R)[0]), "=r"((R)[1]), "=r"((R)[2]), "=r"((R)[3]) : "r"(addr))

// ---------------- K2: GEMM ----------------
__global__ void __launch_bounds__(256, 2)
snn_gemm_kernel(const float* __restrict__ b1) {
    extern __shared__ __align__(16) char smem[];
    __half* stg = (__half*)smem;

    const int tid = threadIdx.x;
    const int l   = tid & 31;
    const int wid = tid >> 5;
    const int wm  = wid & 3;
    const int wn  = wid >> 2;
    const int h0  = blockIdx.x * BN;
    const int b0  = blockIdx.y * BM;

    const int rowA = tid >> 1, caOff = (tid & 1) * 16;
    const int rowB = tid >> 2, cbOff = (tid & 3) * 8;
    const __half* pxh = g_xhi + (size_t)(b0 + rowA) * NIc + caOff;
    const __half* pxl = g_xlo + (size_t)(b0 + rowA) * NIc + caOff;
    const __half* pwh = g_whi + (size_t)(h0 + rowB) * NIc + cbOff;
    const __half* pwl = g_wlo + (size_t)(h0 + rowB) * NIc + cbOff;
    const uint32_t stg0 = smem_u32(stg);
    const uint32_t smA = stg0 + (rowA * 40 + caOff) * 2;
    const uint32_t smB = stg0 + (rowB * 40 + cbOff) * 2;

    auto issue_copy = [&](int s, int buf) {
        const uint32_t so = (uint32_t)buf * STG_B;
        cpasync16(smA + A_HI_B + so,      pxh + s * BK);
        cpasync16(smA + A_HI_B + so + 16, pxh + s * BK + 8);
        cpasync16(smA + A_LO_B + so,      pxl + s * BK);
        cpasync16(smA + A_LO_B + so + 16, pxl + s * BK + 8);
        cpasync16(smB + B_HI_B + so,      pwh + s * BK);
        cpasync16(smB + B_LO_B + so,      pwl + s * BK);
        CP_COMMIT();
    };

    const int mrow = l & 7, msel = l >> 3;
    uint32_t aHi[2], aLo[2];
#pragma unroll
    for (int mt = 0; mt < 2; mt++) {
        int row = wm * 32 + mt * 16 + (msel & 1) * 8 + mrow;
        int kof = (msel >> 1) * 8;
        aHi[mt] = stg0 + A_HI_B + row * 80 + kof * 2;
        aLo[mt] = stg0 + A_LO_B + row * 80 + kof * 2;
    }
    uint32_t bHi[2], bLo[2];
#pragma unroll
    for (int p = 0; p < 2; p++) {
        int n   = wn * 32 + p * 16 + (msel >> 1) * 8 + mrow;
        int kof = (msel & 1) * 8;
        bHi[p] = stg0 + B_HI_B + n * 80 + kof * 2;
        bLo[p] = stg0 + B_LO_B + n * 80 + kof * 2;
    }

    float c[2][4][4];
#pragma unroll
    for (int mt = 0; mt < 2; mt++)
#pragma unroll
        for (int nt = 0; nt < 4; nt++)
#pragma unroll
            for (int r = 0; r < 4; r++) c[mt][nt][r] = 0.0f;

    auto compute_stage = [&](int buf) {
        const uint32_t so = (uint32_t)buf * STG_B;
#pragma unroll
        for (int ks = 0; ks < 2; ks++) {
            const uint32_t ko = so + ks * 32;
            uint32_t ah[2][4], al[2][4], bh[2][4], bl[2][4];
#pragma unroll
            for (int mt = 0; mt < 2; mt++) {
                LDMATRIX_X4(ah[mt], aHi[mt] + ko);
                LDMATRIX_X4(al[mt], aLo[mt] + ko);
            }
#pragma unroll
            for (int p = 0; p < 2; p++) {
                LDMATRIX_X4(bh[p], bHi[p] + ko);
                LDMATRIX_X4(bl[p], bLo[p] + ko);
            }
#pragma unroll
            for (int mt = 0; mt < 2; mt++)
#pragma unroll
                for (int nt = 0; nt < 4; nt++)
                    MMA16816(c[mt][nt], ah[mt], &bh[nt >> 1][(nt & 1) * 2]);
#pragma unroll
            for (int mt = 0; mt < 2; mt++)
#pragma unroll
                for (int nt = 0; nt < 4; nt++)
                    MMA16816(c[mt][nt], ah[mt], &bl[nt >> 1][(nt & 1) * 2]);
#pragma unroll
            for (int mt = 0; mt < 2; mt++)
#pragma unroll
                for (int nt = 0; nt < 4; nt++)
                    MMA16816(c[mt][nt], al[mt], &bh[nt >> 1][(nt & 1) * 2]);
        }
    };

    issue_copy(0, 0);
    issue_copy(1, 1);
#pragma unroll 1
    for (int s = 0; s < NSTAGE; s++) {
        if (s == NSTAGE - 1) { CP_WAIT(0); } else { CP_WAIT(1); }
        __syncthreads();
        if (s + 2 < NSTAGE) issue_copy(s + 2, (s + 2) % PIPE);
        compute_stage(s % PIPE);
    }

    // epilogue: x1 = c + b1 -> gmem
    const int lr = l >> 2, lq = (l & 3) * 2;
    float bb[4][2];
#pragma unroll
    for (int nt = 0; nt < 4; nt++) {
        bb[nt][0] = __ldg(&b1[h0 + wn * 32 + nt * 8 + lq]);
        bb[nt][1] = __ldg(&b1[h0 + wn * 32 + nt * 8 + lq + 1]);
    }
#pragma unroll
    for (int mt = 0; mt < 2; mt++)
#pragma unroll
        for (int rr = 0; rr < 2; rr++) {
            const size_t grow = (size_t)(b0 + wm * 32 + mt * 16 + rr * 8 + lr) * NHc;
#pragma unroll
            for (int nt = 0; nt < 4; nt++) {
                const int gcol = h0 + wn * 32 + nt * 8 + lq;
                float2 v = make_float2(c[mt][nt][rr * 2 + 0] + bb[nt][0],
                                       c[mt][nt][rr * 2 + 1] + bb[nt][1]);
                *(float2*)&g_x1[grow + gcol] = v;
            }
        }
}

// ---------------- K3: LIF recurrence + W2 reduce ----------------
__global__ void __launch_bounds__(256)
snn_lif_kernel(const float* __restrict__ W2,
               const float* __restrict__ beta_p,
               const float* __restrict__ thr,
               float* __restrict__ out) {
    const int gw   = (blockIdx.x * blockDim.x + threadIdx.x) >> 5;  // global warp
    const int lane = threadIdx.x & 31;
    const int b    = gw >> 2;          // batch row
    const int q    = gw & 3;           // 256-col quarter
    const int hb   = q * 256 + lane * 8;

    const float beta = fminf(fmaxf(__ldg(beta_p), 0.0f), 1.0f);

    float x1[8], thv[8], nthv[8], m[8], cnt[8];
    const float* px = g_x1 + (size_t)b * NHc + hb;
    *(float4*)&x1[0] = *(const float4*)(px);
    *(float4*)&x1[4] = *(const float4*)(px + 4);
    *(float4*)&thv[0] = *(const float4*)(thr + hb);
    *(float4*)&thv[4] = *(const float4*)(thr + hb + 4);

#pragma unroll
    for (int e = 0; e < 8; e++) {
        nthv[e] = -thv[e];
        cnt[e]  = 0.0f;
        // step 1 from mem0 = 0: reset = H(0 - thr)
        float s0;
        asm("set.gt.f32.f32 %0, %1, %2;" : "=f"(s0) : "f"(0.0f), "f"(thv[e]));
        m[e] = fmaf(s0, nthv[e], x1[e]);
    }
#pragma unroll 5
    for (int t = 1; t < NSTEPS; t++) {
#pragma unroll
        for (int e = 0; e < 8; e++) {
            float s;
            asm("set.gt.f32.f32 %0, %1, %2;" : "=f"(s) : "f"(m[e]), "f"(thv[e]));
            cnt[e] += s;
            m[e] = fmaf(beta, m[e], fmaf(s, nthv[e], x1[e]));
        }
    }
    float p = 0.0f;
#pragma unroll
    for (int e = 0; e < 8; e++) {
        float s;
        asm("set.gt.f32.f32 %0, %1, %2;" : "=f"(s) : "f"(m[e]), "f"(thv[e]));
        cnt[e] += s;
        p = fmaf(cnt[e], __ldg(&W2[hb + e]), p);
    }
#pragma unroll
    for (int off = 16; off > 0; off >>= 1)
        p += __shfl_down_sync(0xffffffffu, p, off);
    if (lane == 0) atomicAdd(&out[b], p);
}

extern "C" void kernel_launch(void* const* d_in, const int* in_sizes, int n_in,
                              void* d_out, int out_size) {
    const float* x    = (const float*)d_in[0];
    const float* W1   = (const float*)d_in[1];
    const float* b1   = (const float*)d_in[2];
    const float* W2   = (const float*)d_in[3];
    const float* b2   = (const float*)d_in[4];
    const float* beta = (const float*)d_in[5];
    const float* thr  = (const float*)d_in[6];
    float* out = (float*)d_out;

    const int B = in_sizes[0] / NIc;  // 32768

    __half *xhi, *xlo, *whi, *wlo;
    cudaGetSymbolAddress((void**)&xhi, g_xhi);
    cudaGetSymbolAddress((void**)&xlo, g_xlo);
    cudaGetSymbolAddress((void**)&whi, g_whi);
    cudaGetSymbolAddress((void**)&wlo, g_wlo);

    const int nx4 = B * NIc / 4;
    const int nw4 = NHc * NIc / 4;
    cvt_kernel<<<(nx4 + 255) / 256, 256>>>(x, xhi, xlo, nx4);
    cvt_kernel<<<(nw4 + 255) / 256, 256>>>(W1, whi, wlo, nw4);
    init_out_kernel<<<(B + 255) / 256, 256>>>(out, b2, B);

    cudaFuncSetAttribute(snn_gemm_kernel,
                         cudaFuncAttributeMaxDynamicSharedMemorySize, SMEM_TOTAL);

    dim3 grid(NHc / BN, B / BM);
    snn_gemm_kernel<<<grid, 256, SMEM_TOTAL>>>(b1);

    const int warps = B * 4;                 // one warp per (row, quarter)
    snn_lif_kernel<<<warps * 32 / 256, 256>>>(W2, beta, thr, out);
}

// round 7
// speedup vs baseline: 1.5113x; 1.0628x over previous
#include <cuda_runtime.h>
#include <cuda_fp16.h>
#include <cstdint>

// LeakySNN, de-fused:
//  K1 cvt: x,W1 -> fp16 hi/lo split arrays
//  K2 gemm: x1 = x@W1^T + b1, 128x128 block tile, 32x64 warp tile, XOR-swizzled smem
//  K3 lif:  25-step recurrence, f32x2-packed, spk.W2 -> atomicAdd(out)
// Shapes fixed: B=32768, NI=256, NH=1024, NO=1, NUM_STEPS=25.

#define NIc     256
#define NHc     1024
#define BTOT    32768
#define NSTEPS  25
#define BM      128
#define BN      128
#define BK      32
#define NSTAGE  (NIc / BK)   // 8
#define PIPE    3

// stage regions (bytes): 128 rows x 64B each
#define R_AHI   0
#define R_ALO   8192
#define R_BHI   16384
#define R_BLO   24576
#define STG_B   32768
#define SMEM_TOTAL (PIPE * STG_B)   // 98304 -> 2 blocks/SM

typedef unsigned long long u64;

__device__ __half g_xhi[(size_t)BTOT * NIc];
__device__ __half g_xlo[(size_t)BTOT * NIc];
__device__ __half g_whi[(size_t)NHc * NIc];
__device__ __half g_wlo[(size_t)NHc * NIc];
__device__ float  g_x1[(size_t)BTOT * NHc];   // 128 MB scratch

__global__ void cvt_kernel(const float* __restrict__ src,
                           __half* __restrict__ hi, __half* __restrict__ lo,
                           int n4) {
    int i = blockIdx.x * blockDim.x + threadIdx.x;
    if (i >= n4) return;
    float4 v = *((const float4*)src + i);
    __half h0 = __float2half_rn(v.x), h1 = __float2half_rn(v.y);
    __half h2 = __float2half_rn(v.z), h3 = __float2half_rn(v.w);
    __half l0 = __float2half_rn(v.x - __half2float(h0));
    __half l1 = __float2half_rn(v.y - __half2float(h1));
    __half l2 = __float2half_rn(v.z - __half2float(h2));
    __half l3 = __float2half_rn(v.w - __half2float(h3));
    __half2* ph = (__half2*)(hi + (size_t)i * 4);
    __half2* pl = (__half2*)(lo + (size_t)i * 4);
    ph[0] = __halves2half2(h0, h1); ph[1] = __halves2half2(h2, h3);
    pl[0] = __halves2half2(l0, l1); pl[1] = __halves2half2(l2, l3);
}

__global__ void init_out_kernel(float* __restrict__ out,
                                const float* __restrict__ b2, int n) {
    int i = blockIdx.x * blockDim.x + threadIdx.x;
    if (i < n) out[i] = b2[0];
}

__device__ __forceinline__ uint32_t smem_u32(const void* p) {
    uint32_t a;
    asm("{ .reg .u64 t; cvta.to.shared.u64 t, %1; cvt.u32.u64 %0, t; }" : "=r"(a) : "l"(p));
    return a;
}

__device__ __forceinline__ void cpasync16(uint32_t dst, const void* src) {
    asm volatile("cp.async.ca.shared.global [%0], [%1], 16;"
                 :: "r"(dst), "l"(__cvta_generic_to_global(src)) : "memory");
}
#define CP_COMMIT() asm volatile("cp.async.commit_group;" ::: "memory")
#define CP_WAIT(n)  asm volatile("cp.async.wait_group %0;" :: "n"(n) : "memory")

#define MMA16816(C, A, B) \
    asm volatile("mma.sync.aligned.m16n8k16.row.col.f32.f16.f16.f32 " \
        "{%0,%1,%2,%3}, {%4,%5,%6,%7}, {%8,%9}, {%0,%1,%2,%3};" \
        : "+f"((C)[0]), "+f"((C)[1]), "+f"((C)[2]), "+f"((C)[3]) \
        : "r"((A)[0]), "r"((A)[1]), "r"((A)[2]), "r"((A)[3]), \
          "r"((B)[0]), "r"((B)[1]))

#define LDMATRIX_X4(R, addr) \
    asm volatile("ldmatrix.sync.aligned.m8n8.x4.shared.b16 {%0,%1,%2,%3}, [%4];" \
        : "=r"((R)[0]), "=r"((R)[1]), "=r"((R)[2]), "=r"((R)[3]) : "r"(addr))

// swizzled byte offset within a region: row has 4 16B chunks
__device__ __forceinline__ uint32_t swz(int row, int chunk) {
    return (uint32_t)(row * 64 + ((chunk ^ ((row >> 1) & 3)) << 4));
}

// ---------------- K2: GEMM ----------------
__global__ void __launch_bounds__(256, 2)
snn_gemm_kernel(const float* __restrict__ b1) {
    extern __shared__ __align__(16) char smem[];
    const uint32_t stg0 = smem_u32(smem);

    const int tid = threadIdx.x;
    const int l   = tid & 31;
    const int wid = tid >> 5;
    const int wm  = wid & 3;        // 4 warps x 32 rows
    const int wn  = wid >> 2;       // 2 warps x 64 cols
    const int h0  = blockIdx.x * BN;
    const int b0  = blockIdx.y * BM;

    // ---- cp.async staging: thread t -> row t>>1, chunks {2(t&1), 2(t&1)+1} ----
    const int crow  = tid >> 1;
    const int cpair = (tid & 1) * 2;
    const __half* pxh = g_xhi + (size_t)(b0 + crow) * NIc + cpair * 8;
    const __half* pxl = g_xlo + (size_t)(b0 + crow) * NIc + cpair * 8;
    const __half* pwh = g_whi + (size_t)(h0 + crow) * NIc + cpair * 8;
    const __half* pwl = g_wlo + (size_t)(h0 + crow) * NIc + cpair * 8;
    const uint32_t d0 = swz(crow, cpair);       // chunk cpair
    const uint32_t d1 = d0 ^ 16;                // chunk cpair+1 (bit0 toggle)

    auto issue_copy = [&](int s, int buf) {
        const uint32_t so = stg0 + (uint32_t)buf * STG_B;
        cpasync16(so + R_AHI + d0, pxh + s * BK);
        cpasync16(so + R_AHI + d1, pxh + s * BK + 8);
        cpasync16(so + R_ALO + d0, pxl + s * BK);
        cpasync16(so + R_ALO + d1, pxl + s * BK + 8);
        cpasync16(so + R_BHI + d0, pwh + s * BK);
        cpasync16(so + R_BHI + d1, pwh + s * BK + 8);
        cpasync16(so + R_BLO + d0, pwl + s * BK);
        cpasync16(so + R_BLO + d1, pwl + s * BK + 8);
        CP_COMMIT();
    };

    // ---- ldmatrix base addresses (stage 0, ks 0) ----
    const int mrow = l & 7, msel = l >> 3;
    uint32_t aHiAdr[2], aLoAdr[2];
#pragma unroll
    for (int mt = 0; mt < 2; mt++) {
        int row = wm * 32 + mt * 16 + (msel & 1) * 8 + mrow;
        int ch  = msel >> 1;                      // 16B chunk along k
        aHiAdr[mt] = stg0 + R_AHI + swz(row, ch);
        aLoAdr[mt] = stg0 + R_ALO + swz(row, ch);
    }
    uint32_t bHiAdr[4], bLoAdr[4];
#pragma unroll
    for (int p = 0; p < 4; p++) {
        int n  = wn * 64 + p * 16 + (msel >> 1) * 8 + mrow;
        int ch = msel & 1;
        bHiAdr[p] = stg0 + R_BHI + swz(n, ch);
        bLoAdr[p] = stg0 + R_BLO + swz(n, ch);
    }

    float c[2][8][4];
#pragma unroll
    for (int mt = 0; mt < 2; mt++)
#pragma unroll
        for (int nt = 0; nt < 8; nt++)
#pragma unroll
            for (int r = 0; r < 4; r++) c[mt][nt][r] = 0.0f;

    auto compute_stage = [&](int buf) {
        const uint32_t so = (uint32_t)buf * STG_B;
#pragma unroll
        for (int ks = 0; ks < 2; ks++) {
            const uint32_t kx = ks << 5;   // ks=1: chunk bit1 toggles -> addr ^ 32
            uint32_t ah[2][4], al[2][4], bh[4][4], bl[4][4];
#pragma unroll
            for (int mt = 0; mt < 2; mt++) {
                LDMATRIX_X4(ah[mt], (aHiAdr[mt] + so) ^ kx);
                LDMATRIX_X4(al[mt], (aLoAdr[mt] + so) ^ kx);
            }
#pragma unroll
            for (int p = 0; p < 4; p++)
                LDMATRIX_X4(bh[p], (bHiAdr[p] + so) ^ kx);
            // hi*hi
#pragma unroll
            for (int mt = 0; mt < 2; mt++)
#pragma unroll
                for (int nt = 0; nt < 8; nt++)
                    MMA16816(c[mt][nt], ah[mt], &bh[nt >> 1][(nt & 1) * 2]);
            // lo*hi
#pragma unroll
            for (int mt = 0; mt < 2; mt++)
#pragma unroll
                for (int nt = 0; nt < 8; nt++)
                    MMA16816(c[mt][nt], al[mt], &bh[nt >> 1][(nt & 1) * 2]);
#pragma unroll
            for (int p = 0; p < 4; p++)
                LDMATRIX_X4(bl[p], (bLoAdr[p] + so) ^ kx);
            // hi*lo
#pragma unroll
            for (int mt = 0; mt < 2; mt++)
#pragma unroll
                for (int nt = 0; nt < 8; nt++)
                    MMA16816(c[mt][nt], ah[mt], &bl[nt >> 1][(nt & 1) * 2]);
        }
    };

    issue_copy(0, 0);
    issue_copy(1, 1);
#pragma unroll 1
    for (int s = 0; s < NSTAGE; s++) {
        if (s == NSTAGE - 1) { CP_WAIT(0); } else { CP_WAIT(1); }
        __syncthreads();
        if (s + 2 < NSTAGE) issue_copy(s + 2, (s + 2) % PIPE);
        compute_stage(s % PIPE);
    }

    // ---- epilogue: x1 = c + b1 -> gmem ----
    const int lr = l >> 2, lq = (l & 3) * 2;
    float bb[8][2];
#pragma unroll
    for (int nt = 0; nt < 8; nt++) {
        bb[nt][0] = __ldg(&b1[h0 + wn * 64 + nt * 8 + lq]);
        bb[nt][1] = __ldg(&b1[h0 + wn * 64 + nt * 8 + lq + 1]);
    }
#pragma unroll
    for (int mt = 0; mt < 2; mt++)
#pragma unroll
        for (int rr = 0; rr < 2; rr++) {
            const size_t grow = (size_t)(b0 + wm * 32 + mt * 16 + rr * 8 + lr) * NHc;
#pragma unroll
            for (int nt = 0; nt < 8; nt++) {
                const int gcol = h0 + wn * 64 + nt * 8 + lq;
                float2 v = make_float2(c[mt][nt][rr * 2 + 0] + bb[nt][0],
                                       c[mt][nt][rr * 2 + 1] + bb[nt][1]);
                *(float2*)&g_x1[grow + gcol] = v;
            }
        }
}

// ---------------- K3: LIF recurrence (f32x2) + W2 reduce ----------------
__device__ __forceinline__ u64 pk2(float lo, float hi) {
    u64 r;
    asm("mov.b64 %0, {%1, %2};" : "=l"(r) : "f"(lo), "f"(hi));
    return r;
}
__device__ __forceinline__ void upk2(u64 v, float& lo, float& hi) {
    asm("mov.b64 {%0, %1}, %2;" : "=f"(lo), "=f"(hi) : "l"(v));
}
__device__ __forceinline__ u64 fma2(u64 a, u64 b, u64 c) {
    u64 d;
    asm("fma.rn.f32x2 %0, %1, %2, %3;" : "=l"(d) : "l"(a), "l"(b), "l"(c));
    return d;
}
__device__ __forceinline__ void add2(u64& d, u64 a) {
    asm("add.rn.f32x2 %0, %0, %1;" : "+l"(d) : "l"(a));
}
__device__ __forceinline__ float fset_gt(float a, float b) {
    float s;
    asm("set.gt.f32.f32 %0, %1, %2;" : "=f"(s) : "f"(a), "f"(b));
    return s;
}

__global__ void __launch_bounds__(256)
snn_lif_kernel(const float* __restrict__ W2,
               const float* __restrict__ beta_p,
               const float* __restrict__ thr,
               float* __restrict__ out) {
    const int gw   = (blockIdx.x * blockDim.x + threadIdx.x) >> 5;
    const int lane = threadIdx.x & 31;
    const int b    = gw >> 2;
    const int q    = gw & 3;
    const int hb   = q * 256 + lane * 8;

    const float beta = fminf(fmaxf(__ldg(beta_p), 0.0f), 1.0f);
    const u64 beta2 = pk2(beta, beta);

    float x1[8], thv[8];
    const float* px = g_x1 + (size_t)b * NHc + hb;
    *(float4*)&x1[0]  = *(const float4*)(px);
    *(float4*)&x1[4]  = *(const float4*)(px + 4);
    *(float4*)&thv[0] = *(const float4*)(thr + hb);
    *(float4*)&thv[4] = *(const float4*)(thr + hb + 4);

    u64 x12[4], nth2[4], m2[4], cnt2[4];
#pragma unroll
    for (int p = 0; p < 4; p++) {
        x12[p]  = pk2(x1[2 * p], x1[2 * p + 1]);
        nth2[p] = pk2(-thv[2 * p], -thv[2 * p + 1]);
        cnt2[p] = pk2(0.0f, 0.0f);
        // step 1 from mem0 = 0: reset = H(0 - thr)
        u64 sv = pk2(fset_gt(0.0f, thv[2 * p]), fset_gt(0.0f, thv[2 * p + 1]));
        m2[p] = fma2(sv, nth2[p], x12[p]);
    }
#pragma unroll 4
    for (int t = 1; t < NSTEPS; t++) {
#pragma unroll
        for (int p = 0; p < 4; p++) {
            float ma, mb;
            upk2(m2[p], ma, mb);
            u64 sv = pk2(fset_gt(ma, thv[2 * p]), fset_gt(mb, thv[2 * p + 1]));
            add2(cnt2[p], sv);
            m2[p] = fma2(beta2, m2[p], fma2(sv, nth2[p], x12[p]));
        }
    }
    float acc = 0.0f;
#pragma unroll
    for (int p = 0; p < 4; p++) {
        float ma, mb;
        upk2(m2[p], ma, mb);
        u64 sv = pk2(fset_gt(ma, thv[2 * p]), fset_gt(mb, thv[2 * p + 1]));
        add2(cnt2[p], sv);
        float ca, cb;
        upk2(cnt2[p], ca, cb);
        acc = fmaf(ca, __ldg(&W2[hb + 2 * p]), acc);
        acc = fmaf(cb, __ldg(&W2[hb + 2 * p + 1]), acc);
    }
#pragma unroll
    for (int off = 16; off > 0; off >>= 1)
        acc += __shfl_down_sync(0xffffffffu, acc, off);
    if (lane == 0) atomicAdd(&out[b], acc);
}

extern "C" void kernel_launch(void* const* d_in, const int* in_sizes, int n_in,
                              void* d_out, int out_size) {
    const float* x    = (const float*)d_in[0];
    const float* W1   = (const float*)d_in[1];
    const float* b1   = (const float*)d_in[2];
    const float* W2   = (const float*)d_in[3];
    const float* b2   = (const float*)d_in[4];
    const float* beta = (const float*)d_in[5];
    const float* thr  = (const float*)d_in[6];
    float* out = (float*)d_out;

    const int B = in_sizes[0] / NIc;  // 32768

    __half *xhi, *xlo, *whi, *wlo;
    cudaGetSymbolAddress((void**)&xhi, g_xhi);
    cudaGetSymbolAddress((void**)&xlo, g_xlo);
    cudaGetSymbolAddress((void**)&whi, g_whi);
    cudaGetSymbolAddress((void**)&wlo, g_wlo);

    const int nx4 = B * NIc / 4;
    const int nw4 = NHc * NIc / 4;
    cvt_kernel<<<(nx4 + 255) / 256, 256>>>(x, xhi, xlo, nx4);
    cvt_kernel<<<(nw4 + 255) / 256, 256>>>(W1, whi, wlo, nw4);
    init_out_kernel<<<(B + 255) / 256, 256>>>(out, b2, B);

    cudaFuncSetAttribute(snn_gemm_kernel,
                         cudaFuncAttributeMaxDynamicSharedMemorySize, SMEM_TOTAL);

    dim3 grid(NHc / BN, B / BM);   // (8, 256)
    snn_gemm_kernel<<<grid, 256, SMEM_TOTAL>>>(b1);

    const int warps = B * 4;       // one warp per (row, quarter)
    snn_lif_kernel<<<warps * 32 / 256, 256>>>(W2, beta, thr, out);
}

// round 8
// speedup vs baseline: 1.5143x; 1.0019x over previous
#include <cuda_runtime.h>
#include <cuda_fp16.h>
#include <cstdint>

// LeakySNN, de-fused:
//  K1 cvt: x,W1 -> fp16 hi/lo split arrays
//  K2 gemm: x1 = x@W1^T + b1, 128x128 block tile, 32x64 warp tile, XOR-swizzled smem
//  K3 lif:  25-step recurrence, f32x2-packed, spk.W2 -> atomicAdd(out)
// Shapes fixed: B=32768, NI=256, NH=1024, NO=1, NUM_STEPS=25.

#define NIc     256
#define NHc     1024
#define BTOT    32768
#define NSTEPS  25
#define BM      128
#define BN      128
#define BK      32
#define NSTAGE  (NIc / BK)   // 8
#define PIPE    3

// stage regions (bytes): 128 rows x 64B each
#define R_AHI   0
#define R_ALO   8192
#define R_BHI   16384
#define R_BLO   24576
#define STG_B   32768
#define SMEM_TOTAL (PIPE * STG_B)   // 98304 -> 2 blocks/SM

typedef unsigned long long u64;

__device__ __half g_xhi[(size_t)BTOT * NIc];
__device__ __half g_xlo[(size_t)BTOT * NIc];
__device__ __half g_whi[(size_t)NHc * NIc];
__device__ __half g_wlo[(size_t)NHc * NIc];
__device__ float  g_x1[(size_t)BTOT * NHc];   // 128 MB scratch

__global__ void cvt_kernel(const float* __restrict__ src,
                           __half* __restrict__ hi, __half* __restrict__ lo,
                           int n4) {
    int i = blockIdx.x * blockDim.x + threadIdx.x;
    if (i >= n4) return;
    float4 v = *((const float4*)src + i);
    __half h0 = __float2half_rn(v.x), h1 = __float2half_rn(v.y);
    __half h2 = __float2half_rn(v.z), h3 = __float2half_rn(v.w);
    __half l0 = __float2half_rn(v.x - __half2float(h0));
    __half l1 = __float2half_rn(v.y - __half2float(h1));
    __half l2 = __float2half_rn(v.z - __half2float(h2));
    __half l3 = __float2half_rn(v.w - __half2float(h3));
    __half2* ph = (__half2*)(hi + (size_t)i * 4);
    __half2* pl = (__half2*)(lo + (size_t)i * 4);
    ph[0] = __halves2half2(h0, h1); ph[1] = __halves2half2(h2, h3);
    pl[0] = __halves2half2(l0, l1); pl[1] = __halves2half2(l2, l3);
}

__global__ void init_out_kernel(float* __restrict__ out,
                                const float* __restrict__ b2, int n) {
    int i = blockIdx.x * blockDim.x + threadIdx.x;
    if (i < n) out[i] = b2[0];
}

__device__ __forceinline__ uint32_t smem_u32(const void* p) {
    uint32_t a;
    asm("{ .reg .u64 t; cvta.to.shared.u64 t, %1; cvt.u32.u64 %0, t; }" : "=r"(a) : "l"(p));
    return a;
}

__device__ __forceinline__ void cpasync16(uint32_t dst, const void* src) {
    asm volatile("cp.async.ca.shared.global [%0], [%1], 16;"
                 :: "r"(dst), "l"(__cvta_generic_to_global(src)) : "memory");
}
#define CP_COMMIT() asm volatile("cp.async.commit_group;" ::: "memory")
#define CP_WAIT(n)  asm volatile("cp.async.wait_group %0;" :: "n"(n) : "memory")

#define MMA16816(C, A, B) \
    asm volatile("mma.sync.aligned.m16n8k16.row.col.f32.f16.f16.f32 " \
        "{%0,%1,%2,%3}, {%4,%5,%6,%7}, {%8,%9}, {%0,%1,%2,%3};" \
        : "+f"((C)[0]), "+f"((C)[1]), "+f"((C)[2]), "+f"((C)[3]) \
        : "r"((A)[0]), "r"((A)[1]), "r"((A)[2]), "r"((A)[3]), \
          "r"((B)[0]), "r"((B)[1]))

#define LDMATRIX_X4(R, addr) \
    asm volatile("ldmatrix.sync.aligned.m8n8.x4.shared.b16 {%0,%1,%2,%3}, [%4];" \
        : "=r"((R)[0]), "=r"((R)[1]), "=r"((R)[2]), "=r"((R)[3]) : "r"(addr))

// swizzled byte offset within a region: row has 4 16B chunks
__device__ __forceinline__ uint32_t swz(int row, int chunk) {
    return (uint32_t)(row * 64 + ((chunk ^ ((row >> 1) & 3)) << 4));
}

// ---------------- K2: GEMM ----------------
__global__ void __launch_bounds__(256, 2)
snn_gemm_kernel(const float* __restrict__ b1) {
    extern __shared__ __align__(16) char smem[];
    const uint32_t stg0 = smem_u32(smem);

    const int tid = threadIdx.x;
    const int l   = tid & 31;
    const int wid = tid >> 5;
    const int wm  = wid & 3;        // 4 warps x 32 rows
    const int wn  = wid >> 2;       // 2 warps x 64 cols
    const int h0  = blockIdx.x * BN;
    const int b0  = blockIdx.y * BM;

    // ---- cp.async staging: thread t -> row t>>1, chunks {2(t&1), 2(t&1)+1} ----
    const int crow  = tid >> 1;
    const int cpair = (tid & 1) * 2;
    const __half* pxh = g_xhi + (size_t)(b0 + crow) * NIc + cpair * 8;
    const __half* pxl = g_xlo + (size_t)(b0 + crow) * NIc + cpair * 8;
    const __half* pwh = g_whi + (size_t)(h0 + crow) * NIc + cpair * 8;
    const __half* pwl = g_wlo + (size_t)(h0 + crow) * NIc + cpair * 8;
    const uint32_t d0 = swz(crow, cpair);       // chunk cpair
    const uint32_t d1 = d0 ^ 16;                // chunk cpair+1 (bit0 toggle)

    auto issue_copy = [&](int s, int buf) {
        const uint32_t so = stg0 + (uint32_t)buf * STG_B;
        cpasync16(so + R_AHI + d0, pxh + s * BK);
        cpasync16(so + R_AHI + d1, pxh + s * BK + 8);
        cpasync16(so + R_ALO + d0, pxl + s * BK);
        cpasync16(so + R_ALO + d1, pxl + s * BK + 8);
        cpasync16(so + R_BHI + d0, pwh + s * BK);
        cpasync16(so + R_BHI + d1, pwh + s * BK + 8);
        cpasync16(so + R_BLO + d0, pwl + s * BK);
        cpasync16(so + R_BLO + d1, pwl + s * BK + 8);
        CP_COMMIT();
    };

    // ---- ldmatrix base addresses (stage 0, ks 0) ----
    const int mrow = l & 7, msel = l >> 3;
    uint32_t aHiAdr[2], aLoAdr[2];
#pragma unroll
    for (int mt = 0; mt < 2; mt++) {
        int row = wm * 32 + mt * 16 + (msel & 1) * 8 + mrow;
        int ch  = msel >> 1;                      // 16B chunk along k
        aHiAdr[mt] = stg0 + R_AHI + swz(row, ch);
        aLoAdr[mt] = stg0 + R_ALO + swz(row, ch);
    }
    uint32_t bHiAdr[4], bLoAdr[4];
#pragma unroll
    for (int p = 0; p < 4; p++) {
        int n  = wn * 64 + p * 16 + (msel >> 1) * 8 + mrow;
        int ch = msel & 1;
        bHiAdr[p] = stg0 + R_BHI + swz(n, ch);
        bLoAdr[p] = stg0 + R_BLO + swz(n, ch);
    }

    float c[2][8][4];
#pragma unroll
    for (int mt = 0; mt < 2; mt++)
#pragma unroll
        for (int nt = 0; nt < 8; nt++)
#pragma unroll
            for (int r = 0; r < 4; r++) c[mt][nt][r] = 0.0f;

    auto compute_stage = [&](int buf) {
        const uint32_t so = (uint32_t)buf * STG_B;
#pragma unroll
        for (int ks = 0; ks < 2; ks++) {
            const uint32_t kx = ks << 5;   // ks=1: chunk bit1 toggles -> addr ^ 32
            uint32_t ah[2][4], al[2][4], bh[4][4], bl[4][4];
#pragma unroll
            for (int mt = 0; mt < 2; mt++) {
                LDMATRIX_X4(ah[mt], (aHiAdr[mt] + so) ^ kx);
                LDMATRIX_X4(al[mt], (aLoAdr[mt] + so) ^ kx);
            }
#pragma unroll
            for (int p = 0; p < 4; p++)
                LDMATRIX_X4(bh[p], (bHiAdr[p] + so) ^ kx);
            // hi*hi
#pragma unroll
            for (int mt = 0; mt < 2; mt++)
#pragma unroll
                for (int nt = 0; nt < 8; nt++)
                    MMA16816(c[mt][nt], ah[mt], &bh[nt >> 1][(nt & 1) * 2]);
            // lo*hi
#pragma unroll
            for (int mt = 0; mt < 2; mt++)
#pragma unroll
                for (int nt = 0; nt < 8; nt++)
                    MMA16816(c[mt][nt], al[mt], &bh[nt >> 1][(nt & 1) * 2]);
#pragma unroll
            for (int p = 0; p < 4; p++)
                LDMATRIX_X4(bl[p], (bLoAdr[p] + so) ^ kx);
            // hi*lo
#pragma unroll
            for (int mt = 0; mt < 2; mt++)
#pragma unroll
                for (int nt = 0; nt < 8; nt++)
                    MMA16816(c[mt][nt], ah[mt], &bl[nt >> 1][(nt & 1) * 2]);
        }
    };

    issue_copy(0, 0);
    issue_copy(1, 1);
#pragma unroll 1
    for (int s = 0; s < NSTAGE; s++) {
        if (s == NSTAGE - 1) { CP_WAIT(0); } else { CP_WAIT(1); }
        __syncthreads();
        if (s + 2 < NSTAGE) issue_copy(s + 2, (s + 2) % PIPE);
        compute_stage(s % PIPE);
    }

    // ---- epilogue: x1 = c + b1 -> gmem ----
    const int lr = l >> 2, lq = (l & 3) * 2;
    float bb[8][2];
#pragma unroll
    for (int nt = 0; nt < 8; nt++) {
        bb[nt][0] = __ldg(&b1[h0 + wn * 64 + nt * 8 + lq]);
        bb[nt][1] = __ldg(&b1[h0 + wn * 64 + nt * 8 + lq + 1]);
    }
#pragma unroll
    for (int mt = 0; mt < 2; mt++)
#pragma unroll
        for (int rr = 0; rr < 2; rr++) {
            const size_t grow = (size_t)(b0 + wm * 32 + mt * 16 + rr * 8 + lr) * NHc;
#pragma unroll
            for (int nt = 0; nt < 8; nt++) {
                const int gcol = h0 + wn * 64 + nt * 8 + lq;
                float2 v = make_float2(c[mt][nt][rr * 2 + 0] + bb[nt][0],
                                       c[mt][nt][rr * 2 + 1] + bb[nt][1]);
                *(float2*)&g_x1[grow + gcol] = v;
            }
        }
}

// ---------------- K3: LIF recurrence (f32x2) + W2 reduce ----------------
__device__ __forceinline__ u64 pk2(float lo, float hi) {
    u64 r;
    asm("mov.b64 %0, {%1, %2};" : "=l"(r) : "f"(lo), "f"(hi));
    return r;
}
__device__ __forceinline__ void upk2(u64 v, float& lo, float& hi) {
    asm("mov.b64 {%0, %1}, %2;" : "=f"(lo), "=f"(hi) : "l"(v));
}
__device__ __forceinline__ u64 fma2(u64 a, u64 b, u64 c) {
    u64 d;
    asm("fma.rn.f32x2 %0, %1, %2, %3;" : "=l"(d) : "l"(a), "l"(b), "l"(c));
    return d;
}
__device__ __forceinline__ void add2(u64& d, u64 a) {
    asm("add.rn.f32x2 %0, %0, %1;" : "+l"(d) : "l"(a));
}
__device__ __forceinline__ float fset_gt(float a, float b) {
    float s;
    asm("set.gt.f32.f32 %0, %1, %2;" : "=f"(s) : "f"(a), "f"(b));
    return s;
}

__global__ void __launch_bounds__(256)
snn_lif_kernel(const float* __restrict__ W2,
               const float* __restrict__ beta_p,
               const float* __restrict__ thr,
               float* __restrict__ out) {
    const int gw   = (blockIdx.x * blockDim.x + threadIdx.x) >> 5;
    const int lane = threadIdx.x & 31;
    const int b    = gw >> 2;
    const int q    = gw & 3;
    const int hb   = q * 256 + lane * 8;

    const float beta = fminf(fmaxf(__ldg(beta_p), 0.0f), 1.0f);
    const u64 beta2 = pk2(beta, beta);

    float x1[8], thv[8];
    const float* px = g_x1 + (size_t)b * NHc + hb;
    *(float4*)&x1[0]  = *(const float4*)(px);
    *(float4*)&x1[4]  = *(const float4*)(px + 4);
    *(float4*)&thv[0] = *(const float4*)(thr + hb);
    *(float4*)&thv[4] = *(const float4*)(thr + hb + 4);

    u64 x12[4], nth2[4], m2[4], cnt2[4];
#pragma unroll
    for (int p = 0; p < 4; p++) {
        x12[p]  = pk2(x1[2 * p], x1[2 * p + 1]);
        nth2[p] = pk2(-thv[2 * p], -thv[2 * p + 1]);
        cnt2[p] = pk2(0.0f, 0.0f);
        // step 1 from mem0 = 0: reset = H(0 - thr)
        u64 sv = pk2(fset_gt(0.0f, thv[2 * p]), fset_gt(0.0f, thv[2 * p + 1]));
        m2[p] = fma2(sv, nth2[p], x12[p]);
    }
#pragma unroll 4
    for (int t = 1; t < NSTEPS; t++) {
#pragma unroll
        for (int p = 0; p < 4; p++) {
            float ma, mb;
            upk2(m2[p], ma, mb);
            u64 sv = pk2(fset_gt(ma, thv[2 * p]), fset_gt(mb, thv[2 * p + 1]));
            add2(cnt2[p], sv);
            m2[p] = fma2(beta2, m2[p], fma2(sv, nth2[p], x12[p]));
        }
    }
    float acc = 0.0f;
#pragma unroll
    for (int p = 0; p < 4; p++) {
        float ma, mb;
        upk2(m2[p], ma, mb);
        u64 sv = pk2(fset_gt(ma, thv[2 * p]), fset_gt(mb, thv[2 * p + 1]));
        add2(cnt2[p], sv);
        float ca, cb;
        upk2(cnt2[p], ca, cb);
        acc = fmaf(ca, __ldg(&W2[hb + 2 * p]), acc);
        acc = fmaf(cb, __ldg(&W2[hb + 2 * p + 1]), acc);
    }
#pragma unroll
    for (int off = 16; off > 0; off >>= 1)
        acc += __shfl_down_sync(0xffffffffu, acc, off);
    if (lane == 0) atomicAdd(&out[b], acc);
}

extern "C" void kernel_launch(void* const* d_in, const int* in_sizes, int n_in,
                              void* d_out, int out_size) {
    const float* x    = (const float*)d_in[0];
    const float* W1   = (const float*)d_in[1];
    const float* b1   = (const float*)d_in[2];
    const float* W2   = (const float*)d_in[3];
    const float* b2   = (const float*)d_in[4];
    const float* beta = (const float*)d_in[5];
    const float* thr  = (const float*)d_in[6];
    float* out = (float*)d_out;

    const int B = in_sizes[0] / NIc;  // 32768

    __half *xhi, *xlo, *whi, *wlo;
    cudaGetSymbolAddress((void**)&xhi, g_xhi);
    cudaGetSymbolAddress((void**)&xlo, g_xlo);
    cudaGetSymbolAddress((void**)&whi, g_whi);
    cudaGetSymbolAddress((void**)&wlo, g_wlo);

    const int nx4 = B * NIc / 4;
    const int nw4 = NHc * NIc / 4;
    cvt_kernel<<<(nx4 + 255) / 256, 256>>>(x, xhi, xlo, nx4);
    cvt_kernel<<<(nw4 + 255) / 256, 256>>>(W1, whi, wlo, nw4);
    init_out_kernel<<<(B + 255) / 256, 256>>>(out, b2, B);

    cudaFuncSetAttribute(snn_gemm_kernel,
                         cudaFuncAttributeMaxDynamicSharedMemorySize, SMEM_TOTAL);

    dim3 grid(NHc / BN, B / BM);   // (8, 256)
    snn_gemm_kernel<<<grid, 256, SMEM_TOTAL>>>(b1);

    const int warps = B * 4;       // one warp per (row, quarter)
    snn_lif_kernel<<<warps * 32 / 256, 256>>>(W2, beta, thr, out);
}